// round 3
// baseline (speedup 1.0000x reference)
#include <cuda_runtime.h>
#include <cstdint>

#define N_SEQ 8192
#define DH    512
#define DE    128
#define VOCAB 64
#define TMAX  80
#define G3    1536

// ---------------- device-global state (module-static, no runtime allocation) ----------------
__device__ __align__(16) float g_H[2][3][N_SEQ][DH];   // ping-pong hidden states
__device__ __align__(16) float g_X0[N_SEQ][DE];        // embedded previous token
__device__ int g_eos[N_SEQ];
__device__ int g_first[N_SEQ];

// ---------------- init: eos=0, X_gen col0 = SOS, X0 = emb[SOS] ----------------
__global__ void init_kernel(const float* __restrict__ emb, float* __restrict__ Xgen) {
    int t = blockIdx.x * 256 + threadIdx.x;   // N_SEQ*32 threads
    int row = t >> 5, lane = t & 31;
    if (row >= N_SEQ) return;
    float4 e = ((const float4*)(emb + 1 * DE))[lane];
    g_X0[row][lane * 4 + 0] = e.x;
    g_X0[row][lane * 4 + 1] = e.y;
    g_X0[row][lane * 4 + 2] = e.z;
    g_X0[row][lane * 4 + 3] = e.w;
    if (lane == 0) {
        g_eos[row]   = 0;
        g_first[row] = 0;
        Xgen[row * TMAX] = 1.0f;   // SOS (output buffer is float32)
    }
}

// ---------------- h0 = Z @ z2h_w^T + b, replicated to the 3 layers of buffer 0 ----------------
__global__ void __launch_bounds__(256)
h0_kernel(const float* __restrict__ Z, const float* __restrict__ z2h_w,
          const float* __restrict__ z2h_b) {
    __shared__ __align__(16) float Zs[32][DE];
    __shared__ __align__(16) float Ws[32][DE + 1];
    const int m0 = blockIdx.x * 32, j0 = blockIdx.y * 32;
    const int tid = threadIdx.x;
    for (int i = tid; i < 32 * (DE / 4); i += 256) {
        int r = i >> 5, c = i & 31;
        float4 z4 = ((const float4*)(Z + (size_t)(m0 + r) * DE))[c];
        Zs[r][c * 4 + 0] = z4.x; Zs[r][c * 4 + 1] = z4.y;
        Zs[r][c * 4 + 2] = z4.z; Zs[r][c * 4 + 3] = z4.w;
        float4 w4 = ((const float4*)(z2h_w + (size_t)(j0 + r) * DE))[c];
        Ws[r][c * 4 + 0] = w4.x; Ws[r][c * 4 + 1] = w4.y;
        Ws[r][c * 4 + 2] = w4.z; Ws[r][c * 4 + 3] = w4.w;
    }
    __syncthreads();
    const int tx = tid & 31, my = tid >> 5;
    const float b = z2h_b[j0 + tx];
    #pragma unroll
    for (int mi = 0; mi < 4; mi++) {
        int m = my * 4 + mi;
        float acc = b;
        #pragma unroll 8
        for (int k = 0; k < DE; k++) acc = fmaf(Zs[m][k], Ws[tx][k], acc);
        int gm = m0 + m, gj = j0 + tx;
        g_H[0][0][gm][gj] = acc;
        g_H[0][1][gm][gj] = acc;
        g_H[0][2][gm][gj] = acc;
    }
}

// ---------------- fused GRU layer: 64 rows x 32 h-cols per block, scalar fp32 ----------------
// NT GEMM: both activations and weights are k-major, no pre-transpose needed.
#define CHUNK(SRCPTR, SSTRIDE, WPTR, WSTRIDE, KC, ACCN)                               \
    do {                                                                              \
        __syncthreads();                                                              \
        _Pragma("unroll")                                                             \
        for (int it = 0; it < 2; it++) {                                              \
            int idx = tid + 256 * it;                                                 \
            int rr = idx >> 3, cc = idx & 7;                                          \
            float4 v = *(const float4*)((SRCPTR) + (size_t)(m0 + rr) * (SSTRIDE)      \
                                        + (KC) + cc * 4);                             \
            As[rr][cc * 4 + 0] = v.x; As[rr][cc * 4 + 1] = v.y;                       \
            As[rr][cc * 4 + 2] = v.z; As[rr][cc * 4 + 3] = v.w;                       \
        }                                                                             \
        _Pragma("unroll")                                                             \
        for (int it = 0; it < 3; it++) {                                              \
            int idx = tid + 256 * it;                                                 \
            int row = idx >> 3, cc = idx & 7;                                         \
            int wrow = (row >> 5) * DH + j0 + (row & 31);                             \
            float4 v = *(const float4*)((WPTR) + (size_t)wrow * (WSTRIDE)             \
                                        + (KC) + cc * 4);                             \
            Ws[row][cc * 4 + 0] = v.x; Ws[row][cc * 4 + 1] = v.y;                     \
            Ws[row][cc * 4 + 2] = v.z; Ws[row][cc * 4 + 3] = v.w;                     \
        }                                                                             \
        __syncthreads();                                                              \
        _Pragma("unroll")                                                             \
        for (int k = 0; k < 32; k++) {                                                \
            float wr = Ws[tx][k], wz = Ws[32 + tx][k], wn = Ws[64 + tx][k];           \
            _Pragma("unroll")                                                         \
            for (int p = 0; p < 8; p++) {                                             \
                float a = As[my * 8 + p][k];                                          \
                accR[p] = fmaf(a, wr, accR[p]);                                       \
                accZ[p] = fmaf(a, wz, accZ[p]);                                       \
                ACCN[p] = fmaf(a, wn, ACCN[p]);                                       \
            }                                                                         \
        }                                                                             \
    } while (0)

template <int DIN>
__global__ void __launch_bounds__(256)
gru_kernel(int rb, int wb, int layer,
           const float* __restrict__ wih,   // [1536][DIN]  (k-major rows)
           const float* __restrict__ whh,   // [1536][512]
           const float* __restrict__ bih,   // [1536] this layer
           const float* __restrict__ bhh) {
    __shared__ __align__(16) float As[64][33];   // [m][k]: stores conflict-free, reads broadcast
    __shared__ __align__(16) float Ws[96][33];   // [gate*32+j][k]: reads conflict-free

    const float* X    = (DIN == DE) ? &g_X0[0][0] : &g_H[wb][layer - 1][0][0];
    const float* Hin  = &g_H[rb][layer][0][0];
    float*       Hout = &g_H[wb][layer][0][0];

    const int m0 = blockIdx.x * 64;
    const int j0 = blockIdx.y * 32;
    const int tid = threadIdx.x, tx = tid & 31, my = tid >> 5;

    float accR[8], accZ[8], accIN[8], accHN[8];
    #pragma unroll
    for (int p = 0; p < 8; p++) { accR[p] = 0.f; accZ[p] = 0.f; accIN[p] = 0.f; accHN[p] = 0.f; }

    #pragma unroll 1
    for (int c = 0; c < DIN / 32; c++)
        CHUNK(X, DIN, wih, DIN, c * 32, accIN);
    #pragma unroll 1
    for (int c = 0; c < DH / 32; c++)
        CHUNK(Hin, DH, whh, DH, c * 32, accHN);

    const int jj = j0 + tx;
    const float br  = bih[jj] + bhh[jj];
    const float bz  = bih[DH + jj] + bhh[DH + jj];
    const float bin = bih[2 * DH + jj];
    const float bhn = bhh[2 * DH + jj];
    #pragma unroll
    for (int p = 0; p < 8; p++) {
        int m = m0 + my * 8 + p;
        float rv = 1.f / (1.f + expf(-(accR[p] + br)));
        float zv = 1.f / (1.f + expf(-(accZ[p] + bz)));
        float gv = tanhf(accIN[p] + bin + rv * (accHN[p] + bhn));
        float hp = Hin[(size_t)m * DH + jj];
        Hout[(size_t)m * DH + jj] = (1.f - zv) * gv + zv * hp;
    }
}

// ---------------- head: logits -> argmax -> token/eos bookkeeping -> embed next input ----------------
__global__ void __launch_bounds__(256)
head_kernel(int wb,
            const float* __restrict__ h2v_w,  // [64][512]
            const float* __restrict__ h2v_b,  // [64]
            const float* __restrict__ emb,    // [64][128]
            float* __restrict__ Xgen, int t) {
    __shared__ __align__(16) float Hs[8][DH];
    const int wid = threadIdx.x >> 5, lane = threadIdx.x & 31;
    const int row = blockIdx.x * 8 + wid;
    const float* hsrc = &g_H[wb][2][row][0];
    #pragma unroll
    for (int i = 0; i < 4; i++) {
        float4 h4 = ((const float4*)hsrc)[lane + 32 * i];
        Hs[wid][(lane + 32 * i) * 4 + 0] = h4.x;
        Hs[wid][(lane + 32 * i) * 4 + 1] = h4.y;
        Hs[wid][(lane + 32 * i) * 4 + 2] = h4.z;
        Hs[wid][(lane + 32 * i) * 4 + 3] = h4.w;
    }
    __syncwarp();

    float acc0 = h2v_b[lane], acc1 = h2v_b[lane + 32];
    const float* w0 = h2v_w + (size_t)lane * DH;
    const float* w1 = h2v_w + (size_t)(lane + 32) * DH;
    #pragma unroll 8
    for (int k = 0; k < DH; k++) {
        float h = Hs[wid][k];
        acc0 = fmaf(h, w0[k], acc0);
        acc1 = fmaf(h, w1[k], acc1);
    }
    // argmax with first-index-on-tie semantics (matches jnp.argmax)
    float best; int bi;
    if (acc1 > acc0) { best = acc1; bi = lane + 32; } else { best = acc0; bi = lane; }
    #pragma unroll
    for (int off = 16; off > 0; off >>= 1) {
        float ov = __shfl_down_sync(0xffffffffu, best, off);
        int   oi = __shfl_down_sync(0xffffffffu, bi, off);
        if (ov > best || (ov == best && oi < bi)) { best = ov; bi = oi; }
    }
    int xt = __shfl_sync(0xffffffffu, bi, 0);

    if (lane == 0) {
        int pe = g_eos[row];
        Xgen[row * TMAX + t] = (float)(pe ? 0 : xt);   // PAD after eos (float32 output)
        if (!pe && xt == 2) { g_eos[row] = 1; g_first[row] = t; }
    }
    // gather embedding of x_t as next step's layer-0 input (carry uses raw x_t)
    float4 e = ((const float4*)(emb + (size_t)xt * DE))[lane];
    g_X0[row][lane * 4 + 0] = e.x;
    g_X0[row][lane * 4 + 1] = e.y;
    g_X0[row][lane * 4 + 2] = e.z;
    g_X0[row][lane * 4 + 3] = e.w;
}

// ---------------- finalize seq_lens ----------------
__global__ void fin_kernel(float* __restrict__ out, int out_size) {
    int i = blockIdx.x * 256 + threadIdx.x;
    if (i >= N_SEQ) return;
    if (out_size >= N_SEQ * TMAX + N_SEQ) {
        int f = g_first[i];
        out[N_SEQ * TMAX + i] = (float)(f ? (f + 1) : TMAX);
    }
}

// ---------------- launcher ----------------
extern "C" void kernel_launch(void* const* d_in, const int* in_sizes, int n_in,
                              void* d_out, int out_size) {
    (void)in_sizes; (void)n_in;
    const float* Z     = (const float*)d_in[0];
    const float* emb   = (const float*)d_in[1];
    const float* z2h_w = (const float*)d_in[2];
    const float* z2h_b = (const float*)d_in[3];
    const float* w_ih0 = (const float*)d_in[4];   // [1536][128]
    const float* w_ihr = (const float*)d_in[5];   // [2][1536][512]
    const float* w_hh  = (const float*)d_in[6];   // [3][1536][512]
    const float* b_ih  = (const float*)d_in[7];   // [3][1536]
    const float* b_hh  = (const float*)d_in[8];
    const float* h2v_w = (const float*)d_in[9];   // [64][512]
    const float* h2v_b = (const float*)d_in[10];  // [64]
    float* out = (float*)d_out;

    init_kernel<<<(N_SEQ * 32) / 256, 256>>>(emb, out);
    h0_kernel<<<dim3(N_SEQ / 32, DH / 32), 256>>>(Z, z2h_w, z2h_b);

    const size_t WL = (size_t)G3 * DH;            // per-layer w_hh / w_ih_rest slab
    const dim3 ggrid(N_SEQ / 64, DH / 32);

    for (int t = 1; t < TMAX; t++) {
        const int rb = (t - 1) & 1, wb = t & 1;
        gru_kernel<DE><<<ggrid, 256>>>(rb, wb, 0, w_ih0,      w_hh,          b_ih,          b_hh);
        gru_kernel<DH><<<ggrid, 256>>>(rb, wb, 1, w_ihr,      w_hh + WL,     b_ih + G3,     b_hh + G3);
        gru_kernel<DH><<<ggrid, 256>>>(rb, wb, 2, w_ihr + WL, w_hh + 2 * WL, b_ih + 2 * G3, b_hh + 2 * G3);
        head_kernel<<<N_SEQ / 8, 256>>>(wb, h2v_w, h2v_b, emb, out, t);
    }
    fin_kernel<<<N_SEQ / 256, 256>>>(out, out_size);
}

// round 4
// speedup vs baseline: 1.2718x; 1.2718x over previous
#include <cuda_runtime.h>
#include <cstdint>

#define N_SEQ 8192
#define DH    512
#define DE    128
#define VOCAB 64
#define TMAX  80
#define G3    1536
#define PADA  66   // float stride of one k-row of the A tile (pair-aligned, low-conflict)

typedef unsigned long long u64;

// ---------------- device-global state (module-static, no runtime allocation) ----------------
__device__ __align__(16) float g_H[2][3][N_SEQ][DH];   // ping-pong hidden states
__device__ __align__(16) float g_X0[N_SEQ][DE];        // embedded previous token
__device__ int g_eos[N_SEQ];
__device__ int g_first[N_SEQ];
__device__ int g_tdone[N_SEQ / 64];                    // finished rows per 64-row tile

// ---------------- f32x2 helpers ----------------
__device__ __forceinline__ u64 pack2(float x) {
    u64 r;
    asm("mov.b64 %0, {%1, %1};" : "=l"(r) : "f"(x));
    return r;
}
__device__ __forceinline__ float2 unpack2(u64 v) {
    float lo, hi;
    asm("mov.b64 {%0, %1}, %2;" : "=f"(lo), "=f"(hi) : "l"(v));
    return make_float2(lo, hi);
}
#define FMA2(acc, a, w) \
    asm("fma.rn.f32x2 %0, %1, %2, %0;" : "+l"(acc) : "l"(a), "l"(w))

// ---------------- init: eos=0, X_gen col0 = SOS, X0 = emb[SOS] ----------------
__global__ void init_kernel(const float* __restrict__ emb, float* __restrict__ Xgen) {
    int t = blockIdx.x * 256 + threadIdx.x;   // N_SEQ*32 threads
    int row = t >> 5, lane = t & 31;
    if (row >= N_SEQ) return;
    float4 e = ((const float4*)(emb + 1 * DE))[lane];
    g_X0[row][lane * 4 + 0] = e.x;
    g_X0[row][lane * 4 + 1] = e.y;
    g_X0[row][lane * 4 + 2] = e.z;
    g_X0[row][lane * 4 + 3] = e.w;
    if (lane == 0) {
        g_eos[row]   = 0;
        g_first[row] = 0;
        Xgen[row * TMAX] = 1.0f;   // SOS (output buffer is float32)
        if (row < N_SEQ / 64) g_tdone[row] = 0;
    }
}

// ---------------- h0 = Z @ z2h_w^T + b, replicated to the 3 layers of buffer 0 ----------------
__global__ void __launch_bounds__(256)
h0_kernel(const float* __restrict__ Z, const float* __restrict__ z2h_w,
          const float* __restrict__ z2h_b) {
    __shared__ __align__(16) float Zs[32][DE];
    __shared__ __align__(16) float Ws[32][DE + 1];
    const int m0 = blockIdx.x * 32, j0 = blockIdx.y * 32;
    const int tid = threadIdx.x;
    for (int i = tid; i < 32 * (DE / 4); i += 256) {
        int r = i >> 5, c = i & 31;
        float4 z4 = ((const float4*)(Z + (size_t)(m0 + r) * DE))[c];
        Zs[r][c * 4 + 0] = z4.x; Zs[r][c * 4 + 1] = z4.y;
        Zs[r][c * 4 + 2] = z4.z; Zs[r][c * 4 + 3] = z4.w;
        float4 w4 = ((const float4*)(z2h_w + (size_t)(j0 + r) * DE))[c];
        Ws[r][c * 4 + 0] = w4.x; Ws[r][c * 4 + 1] = w4.y;
        Ws[r][c * 4 + 2] = w4.z; Ws[r][c * 4 + 3] = w4.w;
    }
    __syncthreads();
    const int tx = tid & 31, my = tid >> 5;
    const float b = z2h_b[j0 + tx];
    #pragma unroll
    for (int mi = 0; mi < 4; mi++) {
        int m = my * 4 + mi;
        float acc = b;
        #pragma unroll 8
        for (int k = 0; k < DE; k++) acc = fmaf(Zs[m][k], Ws[tx][k], acc);
        int gm = m0 + m, gj = j0 + tx;
        g_H[0][0][gm][gj] = acc;
        g_H[0][1][gm][gj] = acc;
        g_H[0][2][gm][gj] = acc;
    }
}

// ---------------- fused GRU layer: 64 rows x 32 h-cols per block, f32x2 packed FMA ----------------
// A tile As2f[k][rr]: store addressing identical to the proven scalar version; reads are
// 8-byte broadcast loads of row-pairs. Weights Ws[gate*32+j][k] conflict-free as before.
#define CHUNK(SRCPTR, SSTRIDE, WPTR, WSTRIDE, KC, ACCN)                               \
    do {                                                                              \
        __syncthreads();                                                              \
        _Pragma("unroll")                                                             \
        for (int it = 0; it < 2; it++) {                                              \
            int idx = tid + 256 * it;                                                 \
            int rr = idx >> 3, cc = idx & 7;                                          \
            float4 v = *(const float4*)((SRCPTR) + (size_t)(m0 + rr) * (SSTRIDE)      \
                                        + (KC) + cc * 4);                             \
            As2f[(cc * 4 + 0) * PADA + rr] = v.x;                                     \
            As2f[(cc * 4 + 1) * PADA + rr] = v.y;                                     \
            As2f[(cc * 4 + 2) * PADA + rr] = v.z;                                     \
            As2f[(cc * 4 + 3) * PADA + rr] = v.w;                                     \
        }                                                                             \
        _Pragma("unroll")                                                             \
        for (int it = 0; it < 3; it++) {                                              \
            int idx = tid + 256 * it;                                                 \
            int row = idx >> 3, cc = idx & 7;                                         \
            int wrow = (row >> 5) * DH + j0 + (row & 31);                             \
            float4 v = *(const float4*)((WPTR) + (size_t)wrow * (WSTRIDE)             \
                                        + (KC) + cc * 4);                             \
            Ws[row][cc * 4 + 0] = v.x; Ws[row][cc * 4 + 1] = v.y;                     \
            Ws[row][cc * 4 + 2] = v.z; Ws[row][cc * 4 + 3] = v.w;                     \
        }                                                                             \
        __syncthreads();                                                              \
        _Pragma("unroll")                                                             \
        for (int k = 0; k < 32; k++) {                                                \
            u64 wr2 = pack2(Ws[tx][k]);                                               \
            u64 wz2 = pack2(Ws[32 + tx][k]);                                          \
            u64 wn2 = pack2(Ws[64 + tx][k]);                                          \
            const u64* ap = (const u64*)(As2f + k * PADA) + my * 4;                   \
            _Pragma("unroll")                                                         \
            for (int p = 0; p < 4; p++) {                                             \
                u64 a2 = ap[p];                                                       \
                FMA2(accR[p], a2, wr2);                                               \
                FMA2(accZ[p], a2, wz2);                                               \
                FMA2(ACCN[p], a2, wn2);                                               \
            }                                                                         \
        }                                                                             \
    } while (0)

template <int DIN>
__global__ void __launch_bounds__(256)
gru_kernel(int rb, int wb, int layer,
           const float* __restrict__ wih,   // [1536][DIN]  (k-major rows)
           const float* __restrict__ whh,   // [1536][512]
           const float* __restrict__ bih,   // [1536] this layer
           const float* __restrict__ bhh) {
    __shared__ __align__(16) float As2f[32 * PADA];   // [k][m] pair-packed
    __shared__ __align__(16) float Ws[96][33];        // [gate*32+j][k]

    const int m0 = blockIdx.x * 64;
    if (g_tdone[m0 >> 6] >= 64) return;               // whole tile finished: unobservable

    const float* X    = (DIN == DE) ? &g_X0[0][0] : &g_H[wb][layer - 1][0][0];
    const float* Hin  = &g_H[rb][layer][0][0];
    float*       Hout = &g_H[wb][layer][0][0];

    const int j0 = blockIdx.y * 32;
    const int tid = threadIdx.x, tx = tid & 31, my = tid >> 5;

    u64 accR[4]  = {0, 0, 0, 0}, accZ[4]  = {0, 0, 0, 0};
    u64 accIN[4] = {0, 0, 0, 0}, accHN[4] = {0, 0, 0, 0};

    #pragma unroll 1
    for (int c = 0; c < DIN / 32; c++)
        CHUNK(X, DIN, wih, DIN, c * 32, accIN);
    #pragma unroll 1
    for (int c = 0; c < DH / 32; c++)
        CHUNK(Hin, DH, whh, DH, c * 32, accHN);

    const int jj = j0 + tx;
    const float br  = bih[jj] + bhh[jj];
    const float bz  = bih[DH + jj] + bhh[DH + jj];
    const float bin = bih[2 * DH + jj];
    const float bhn = bhh[2 * DH + jj];
    #pragma unroll
    for (int p = 0; p < 4; p++) {
        float2 fr = unpack2(accR[p]), fz = unpack2(accZ[p]);
        float2 fi = unpack2(accIN[p]), fh = unpack2(accHN[p]);
        int m = m0 + (my * 4 + p) * 2;
        {
            float rv = 1.f / (1.f + expf(-(fr.x + br)));
            float zv = 1.f / (1.f + expf(-(fz.x + bz)));
            float gv = tanhf(fi.x + bin + rv * (fh.x + bhn));
            float hp = Hin[(size_t)m * DH + jj];
            Hout[(size_t)m * DH + jj] = (1.f - zv) * gv + zv * hp;
        }
        {
            float rv = 1.f / (1.f + expf(-(fr.y + br)));
            float zv = 1.f / (1.f + expf(-(fz.y + bz)));
            float gv = tanhf(fi.y + bin + rv * (fh.y + bhn));
            float hp = Hin[(size_t)(m + 1) * DH + jj];
            Hout[(size_t)(m + 1) * DH + jj] = (1.f - zv) * gv + zv * hp;
        }
    }
}

// ---------------- head: logits -> argmax -> token/eos bookkeeping -> embed next input ----------------
__global__ void __launch_bounds__(256)
head_kernel(int wb,
            const float* __restrict__ h2v_w,  // [64][512]
            const float* __restrict__ h2v_b,  // [64]
            const float* __restrict__ emb,    // [64][128]
            float* __restrict__ Xgen, int t) {
    __shared__ __align__(16) float Hs[8][DH];
    const int wid = threadIdx.x >> 5, lane = threadIdx.x & 31;
    const int row = blockIdx.x * 8 + wid;

    const int pe = g_eos[row];                 // warp-uniform
    if (pe) {                                  // finished row: output frozen at PAD
        if (lane == 0) Xgen[row * TMAX + t] = 0.0f;
        return;
    }

    const float* hsrc = &g_H[wb][2][row][0];
    #pragma unroll
    for (int i = 0; i < 4; i++) {
        float4 h4 = ((const float4*)hsrc)[lane + 32 * i];
        Hs[wid][(lane + 32 * i) * 4 + 0] = h4.x;
        Hs[wid][(lane + 32 * i) * 4 + 1] = h4.y;
        Hs[wid][(lane + 32 * i) * 4 + 2] = h4.z;
        Hs[wid][(lane + 32 * i) * 4 + 3] = h4.w;
    }
    __syncwarp();

    float acc0 = h2v_b[lane], acc1 = h2v_b[lane + 32];
    const float* w0 = h2v_w + (size_t)lane * DH;
    const float* w1 = h2v_w + (size_t)(lane + 32) * DH;
    #pragma unroll 8
    for (int k = 0; k < DH; k++) {
        float h = Hs[wid][k];
        acc0 = fmaf(h, w0[k], acc0);
        acc1 = fmaf(h, w1[k], acc1);
    }
    // argmax with first-index-on-tie semantics (matches jnp.argmax)
    float best; int bi;
    if (acc1 > acc0) { best = acc1; bi = lane + 32; } else { best = acc0; bi = lane; }
    #pragma unroll
    for (int off = 16; off > 0; off >>= 1) {
        float ov = __shfl_down_sync(0xffffffffu, best, off);
        int   oi = __shfl_down_sync(0xffffffffu, bi, off);
        if (ov > best || (ov == best && oi < bi)) { best = ov; bi = oi; }
    }
    int xt = __shfl_sync(0xffffffffu, bi, 0);

    if (lane == 0) {
        Xgen[row * TMAX + t] = (float)xt;       // live row: write token (EOS itself included)
        if (xt == 2) {                          // first EOS for this row
            g_eos[row] = 1;
            g_first[row] = t;
            atomicAdd(&g_tdone[row >> 6], 1);
        }
    }
    // gather embedding of x_t as next step's layer-0 input (carry uses raw x_t)
    float4 e = ((const float4*)(emb + (size_t)xt * DE))[lane];
    g_X0[row][lane * 4 + 0] = e.x;
    g_X0[row][lane * 4 + 1] = e.y;
    g_X0[row][lane * 4 + 2] = e.z;
    g_X0[row][lane * 4 + 3] = e.w;
}

// ---------------- finalize seq_lens ----------------
__global__ void fin_kernel(float* __restrict__ out, int out_size) {
    int i = blockIdx.x * 256 + threadIdx.x;
    if (i >= N_SEQ) return;
    if (out_size >= N_SEQ * TMAX + N_SEQ) {
        int f = g_first[i];
        out[N_SEQ * TMAX + i] = (float)(f ? (f + 1) : TMAX);
    }
}

// ---------------- launcher ----------------
extern "C" void kernel_launch(void* const* d_in, const int* in_sizes, int n_in,
                              void* d_out, int out_size) {
    (void)in_sizes; (void)n_in;
    const float* Z     = (const float*)d_in[0];
    const float* emb   = (const float*)d_in[1];
    const float* z2h_w = (const float*)d_in[2];
    const float* z2h_b = (const float*)d_in[3];
    const float* w_ih0 = (const float*)d_in[4];   // [1536][128]
    const float* w_ihr = (const float*)d_in[5];   // [2][1536][512]
    const float* w_hh  = (const float*)d_in[6];   // [3][1536][512]
    const float* b_ih  = (const float*)d_in[7];   // [3][1536]
    const float* b_hh  = (const float*)d_in[8];
    const float* h2v_w = (const float*)d_in[9];   // [64][512]
    const float* h2v_b = (const float*)d_in[10];  // [64]
    float* out = (float*)d_out;

    init_kernel<<<(N_SEQ * 32) / 256, 256>>>(emb, out);
    h0_kernel<<<dim3(N_SEQ / 32, DH / 32), 256>>>(Z, z2h_w, z2h_b);

    const size_t WL = (size_t)G3 * DH;            // per-layer w_hh / w_ih_rest slab
    const dim3 ggrid(N_SEQ / 64, DH / 32);

    for (int t = 1; t < TMAX; t++) {
        const int rb = (t - 1) & 1, wb = t & 1;
        gru_kernel<DE><<<ggrid, 256>>>(rb, wb, 0, w_ih0,      w_hh,          b_ih,          b_hh);
        gru_kernel<DH><<<ggrid, 256>>>(rb, wb, 1, w_ihr,      w_hh + WL,     b_ih + G3,     b_hh + G3);
        gru_kernel<DH><<<ggrid, 256>>>(rb, wb, 2, w_ihr + WL, w_hh + 2 * WL, b_ih + 2 * G3, b_hh + 2 * G3);
        head_kernel<<<N_SEQ / 8, 256>>>(wb, h2v_w, h2v_b, emb, out, t);
    }
    fin_kernel<<<N_SEQ / 256, 256>>>(out, out_size);
}

// round 5
// speedup vs baseline: 1.3608x; 1.0699x over previous
#include <cuda_runtime.h>
#include <cstdint>

#define N_SEQ 8192
#define DH    512
#define DE    128
#define VOCAB 64
#define TMAX  80
#define G3    1536
#define PADM  130  // float stride of one k-row of the A tile (even: u64-aligned pairs)

typedef unsigned long long u64;

// ---------------- device-global state (module-static, no runtime allocation) ----------------
__device__ __align__(16) float g_H[2][3][N_SEQ][DH];   // ping-pong hidden states
__device__ __align__(16) float g_X0[N_SEQ][DE];        // embedded previous token
__device__ int g_eos[N_SEQ];
__device__ int g_first[N_SEQ];
__device__ int g_tdone[N_SEQ / 128];                   // finished rows per 128-row tile

// ---------------- f32x2 helpers ----------------
__device__ __forceinline__ u64 pack2(float x) {
    u64 r;
    asm("mov.b64 %0, {%1, %1};" : "=l"(r) : "f"(x));
    return r;
}
__device__ __forceinline__ float2 unpack2(u64 v) {
    float lo, hi;
    asm("mov.b64 {%0, %1}, %2;" : "=f"(lo), "=f"(hi) : "l"(v));
    return make_float2(lo, hi);
}
#define FMA2(acc, a, w) \
    asm("fma.rn.f32x2 %0, %1, %2, %0;" : "+l"(acc) : "l"(a), "l"(w))

// ---------------- init: eos=0, X_gen col0 = SOS, X0 = emb[SOS] ----------------
__global__ void init_kernel(const float* __restrict__ emb, float* __restrict__ Xgen) {
    int t = blockIdx.x * 256 + threadIdx.x;   // N_SEQ*32 threads
    int row = t >> 5, lane = t & 31;
    if (row >= N_SEQ) return;
    float4 e = ((const float4*)(emb + 1 * DE))[lane];
    g_X0[row][lane * 4 + 0] = e.x;
    g_X0[row][lane * 4 + 1] = e.y;
    g_X0[row][lane * 4 + 2] = e.z;
    g_X0[row][lane * 4 + 3] = e.w;
    if (lane == 0) {
        g_eos[row]   = 0;
        g_first[row] = 0;
        Xgen[row * TMAX] = 1.0f;   // SOS (output buffer is float32)
        if (row < N_SEQ / 128) g_tdone[row] = 0;
    }
}

// ---------------- h0 = Z @ z2h_w^T + b, replicated to the 3 layers of buffer 0 ----------------
__global__ void __launch_bounds__(256)
h0_kernel(const float* __restrict__ Z, const float* __restrict__ z2h_w,
          const float* __restrict__ z2h_b) {
    __shared__ __align__(16) float Zs[32][DE];
    __shared__ __align__(16) float Ws[32][DE + 1];
    const int m0 = blockIdx.x * 32, j0 = blockIdx.y * 32;
    const int tid = threadIdx.x;
    for (int i = tid; i < 32 * (DE / 4); i += 256) {
        int r = i >> 5, c = i & 31;
        float4 z4 = ((const float4*)(Z + (size_t)(m0 + r) * DE))[c];
        Zs[r][c * 4 + 0] = z4.x; Zs[r][c * 4 + 1] = z4.y;
        Zs[r][c * 4 + 2] = z4.z; Zs[r][c * 4 + 3] = z4.w;
        float4 w4 = ((const float4*)(z2h_w + (size_t)(j0 + r) * DE))[c];
        Ws[r][c * 4 + 0] = w4.x; Ws[r][c * 4 + 1] = w4.y;
        Ws[r][c * 4 + 2] = w4.z; Ws[r][c * 4 + 3] = w4.w;
    }
    __syncthreads();
    const int tx = tid & 31, my = tid >> 5;
    const float b = z2h_b[j0 + tx];
    #pragma unroll
    for (int mi = 0; mi < 4; mi++) {
        int m = my * 4 + mi;
        float acc = b;
        #pragma unroll 8
        for (int k = 0; k < DE; k++) acc = fmaf(Zs[m][k], Ws[tx][k], acc);
        int gm = m0 + m, gj = j0 + tx;
        g_H[0][0][gm][gj] = acc;
        g_H[0][1][gm][gj] = acc;
        g_H[0][2][gm][gj] = acc;
    }
}

// ---------------- fused GRU layer: 128 rows x 32 h-cols per block, f32x2 packed FMA ----------------
// A tile As2f[k][m] (stride PADM, m-pairs read as broadcast LDS.64).
// W tile Ws[gate*32+j][k] stride 34 (even): k-pairs read as conflict-free LDS.64.
#define CHUNK(SRCPTR, SSTRIDE, WPTR, WSTRIDE, KC, ACCN)                               \
    do {                                                                              \
        __syncthreads();                                                              \
        _Pragma("unroll")                                                             \
        for (int it = 0; it < 4; it++) {                                              \
            int idx = tid + 256 * it;                                                 \
            int rr = idx >> 3, cc = idx & 7;                                          \
            float4 v = *(const float4*)((SRCPTR) + (size_t)(m0 + rr) * (SSTRIDE)      \
                                        + (KC) + cc * 4);                             \
            As2f[(cc * 4 + 0) * PADM + rr] = v.x;                                     \
            As2f[(cc * 4 + 1) * PADM + rr] = v.y;                                     \
            As2f[(cc * 4 + 2) * PADM + rr] = v.z;                                     \
            As2f[(cc * 4 + 3) * PADM + rr] = v.w;                                     \
        }                                                                             \
        _Pragma("unroll")                                                             \
        for (int it = 0; it < 3; it++) {                                              \
            int idx = tid + 256 * it;                                                 \
            int row = idx >> 3, cc = idx & 7;                                         \
            int wrow = (row >> 5) * DH + j0 + (row & 31);                             \
            float4 v = *(const float4*)((WPTR) + (size_t)wrow * (WSTRIDE)             \
                                        + (KC) + cc * 4);                             \
            Ws[row][cc * 4 + 0] = v.x; Ws[row][cc * 4 + 1] = v.y;                     \
            Ws[row][cc * 4 + 2] = v.z; Ws[row][cc * 4 + 3] = v.w;                     \
        }                                                                             \
        __syncthreads();                                                              \
        _Pragma("unroll")                                                             \
        for (int k = 0; k < 32; k += 2) {                                             \
            float2 wrp = unpack2(*(const u64*)&Ws[tx][k]);                            \
            float2 wzp = unpack2(*(const u64*)&Ws[32 + tx][k]);                       \
            float2 wnp = unpack2(*(const u64*)&Ws[64 + tx][k]);                       \
            u64 wr0 = pack2(wrp.x), wr1 = pack2(wrp.y);                               \
            u64 wz0 = pack2(wzp.x), wz1 = pack2(wzp.y);                               \
            u64 wn0 = pack2(wnp.x), wn1 = pack2(wnp.y);                               \
            const u64* a0p = (const u64*)(As2f + k * PADM) + my * 8;                  \
            const u64* a1p = (const u64*)(As2f + (k + 1) * PADM) + my * 8;            \
            _Pragma("unroll")                                                         \
            for (int p = 0; p < 8; p++) {                                             \
                u64 a0 = a0p[p];                                                      \
                FMA2(accR[p], a0, wr0);                                               \
                FMA2(accZ[p], a0, wz0);                                               \
                FMA2(ACCN[p], a0, wn0);                                               \
                u64 a1 = a1p[p];                                                      \
                FMA2(accR[p], a1, wr1);                                               \
                FMA2(accZ[p], a1, wz1);                                               \
                FMA2(ACCN[p], a1, wn1);                                               \
            }                                                                         \
        }                                                                             \
    } while (0)

template <int DIN>
__global__ void __launch_bounds__(256, 2)
gru_kernel(int rb, int wb, int layer,
           const float* __restrict__ wih,   // [1536][DIN]  (k-major rows)
           const float* __restrict__ whh,   // [1536][512]
           const float* __restrict__ bih,   // [1536] this layer
           const float* __restrict__ bhh) {
    __shared__ __align__(16) float As2f[32 * PADM];   // [k][m] pair-packed (128 rows)
    __shared__ __align__(16) float Ws[96][34];        // [gate*32+j][k] (even stride)

    const int m0 = blockIdx.x * 128;
    if (g_tdone[m0 >> 7] >= 128) return;              // whole tile finished: unobservable

    const float* X    = (DIN == DE) ? &g_X0[0][0] : &g_H[wb][layer - 1][0][0];
    const float* Hin  = &g_H[rb][layer][0][0];
    float*       Hout = &g_H[wb][layer][0][0];

    const int j0 = blockIdx.y * 32;
    const int tid = threadIdx.x, tx = tid & 31, my = tid >> 5;

    u64 accR[8], accZ[8], accIN[8], accHN[8];
    #pragma unroll
    for (int p = 0; p < 8; p++) { accR[p] = 0; accZ[p] = 0; accIN[p] = 0; accHN[p] = 0; }

    #pragma unroll 1
    for (int c = 0; c < DIN / 32; c++)
        CHUNK(X, DIN, wih, DIN, c * 32, accIN);
    #pragma unroll 1
    for (int c = 0; c < DH / 32; c++)
        CHUNK(Hin, DH, whh, DH, c * 32, accHN);

    const int jj = j0 + tx;
    const float br  = bih[jj] + bhh[jj];
    const float bz  = bih[DH + jj] + bhh[DH + jj];
    const float bin = bih[2 * DH + jj];
    const float bhn = bhh[2 * DH + jj];
    #pragma unroll
    for (int p = 0; p < 8; p++) {
        float2 fr = unpack2(accR[p]), fz = unpack2(accZ[p]);
        float2 fi = unpack2(accIN[p]), fh = unpack2(accHN[p]);
        int m = m0 + my * 16 + 2 * p;
        {
            float rv = 1.f / (1.f + expf(-(fr.x + br)));
            float zv = 1.f / (1.f + expf(-(fz.x + bz)));
            float gv = tanhf(fi.x + bin + rv * (fh.x + bhn));
            float hp = Hin[(size_t)m * DH + jj];
            Hout[(size_t)m * DH + jj] = (1.f - zv) * gv + zv * hp;
        }
        {
            float rv = 1.f / (1.f + expf(-(fr.y + br)));
            float zv = 1.f / (1.f + expf(-(fz.y + bz)));
            float gv = tanhf(fi.y + bin + rv * (fh.y + bhn));
            float hp = Hin[(size_t)(m + 1) * DH + jj];
            Hout[(size_t)(m + 1) * DH + jj] = (1.f - zv) * gv + zv * hp;
        }
    }
}

// ---------------- head: logits -> argmax -> token/eos bookkeeping -> embed next input ----------------
__global__ void __launch_bounds__(256)
head_kernel(int wb,
            const float* __restrict__ h2v_w,  // [64][512]
            const float* __restrict__ h2v_b,  // [64]
            const float* __restrict__ emb,    // [64][128]
            float* __restrict__ Xgen, int t) {
    __shared__ __align__(16) float Hs[8][DH];
    const int wid = threadIdx.x >> 5, lane = threadIdx.x & 31;
    const int row = blockIdx.x * 8 + wid;

    const int pe = g_eos[row];                 // warp-uniform
    if (pe) {                                  // finished row: output frozen at PAD
        if (lane == 0) Xgen[row * TMAX + t] = 0.0f;
        return;
    }

    const float* hsrc = &g_H[wb][2][row][0];
    #pragma unroll
    for (int i = 0; i < 4; i++) {
        float4 h4 = ((const float4*)hsrc)[lane + 32 * i];
        Hs[wid][(lane + 32 * i) * 4 + 0] = h4.x;
        Hs[wid][(lane + 32 * i) * 4 + 1] = h4.y;
        Hs[wid][(lane + 32 * i) * 4 + 2] = h4.z;
        Hs[wid][(lane + 32 * i) * 4 + 3] = h4.w;
    }
    __syncwarp();

    float acc0 = h2v_b[lane], acc1 = h2v_b[lane + 32];
    const float* w0 = h2v_w + (size_t)lane * DH;
    const float* w1 = h2v_w + (size_t)(lane + 32) * DH;
    #pragma unroll 8
    for (int k = 0; k < DH; k++) {
        float h = Hs[wid][k];
        acc0 = fmaf(h, w0[k], acc0);
        acc1 = fmaf(h, w1[k], acc1);
    }
    // argmax with first-index-on-tie semantics (matches jnp.argmax)
    float best; int bi;
    if (acc1 > acc0) { best = acc1; bi = lane + 32; } else { best = acc0; bi = lane; }
    #pragma unroll
    for (int off = 16; off > 0; off >>= 1) {
        float ov = __shfl_down_sync(0xffffffffu, best, off);
        int   oi = __shfl_down_sync(0xffffffffu, bi, off);
        if (ov > best || (ov == best && oi < bi)) { best = ov; bi = oi; }
    }
    int xt = __shfl_sync(0xffffffffu, bi, 0);

    if (lane == 0) {
        Xgen[row * TMAX + t] = (float)xt;       // live row: write token (EOS itself included)
        if (xt == 2) {                          // first EOS for this row
            g_eos[row] = 1;
            g_first[row] = t;
            atomicAdd(&g_tdone[row >> 7], 1);
        }
    }
    // gather embedding of x_t as next step's layer-0 input (carry uses raw x_t)
    float4 e = ((const float4*)(emb + (size_t)xt * DE))[lane];
    g_X0[row][lane * 4 + 0] = e.x;
    g_X0[row][lane * 4 + 1] = e.y;
    g_X0[row][lane * 4 + 2] = e.z;
    g_X0[row][lane * 4 + 3] = e.w;
}

// ---------------- finalize seq_lens ----------------
__global__ void fin_kernel(float* __restrict__ out, int out_size) {
    int i = blockIdx.x * 256 + threadIdx.x;
    if (i >= N_SEQ) return;
    if (out_size >= N_SEQ * TMAX + N_SEQ) {
        int f = g_first[i];
        out[N_SEQ * TMAX + i] = (float)(f ? (f + 1) : TMAX);
    }
}

// ---------------- launcher ----------------
extern "C" void kernel_launch(void* const* d_in, const int* in_sizes, int n_in,
                              void* d_out, int out_size) {
    (void)in_sizes; (void)n_in;
    const float* Z     = (const float*)d_in[0];
    const float* emb   = (const float*)d_in[1];
    const float* z2h_w = (const float*)d_in[2];
    const float* z2h_b = (const float*)d_in[3];
    const float* w_ih0 = (const float*)d_in[4];   // [1536][128]
    const float* w_ihr = (const float*)d_in[5];   // [2][1536][512]
    const float* w_hh  = (const float*)d_in[6];   // [3][1536][512]
    const float* b_ih  = (const float*)d_in[7];   // [3][1536]
    const float* b_hh  = (const float*)d_in[8];
    const float* h2v_w = (const float*)d_in[9];   // [64][512]
    const float* h2v_b = (const float*)d_in[10];  // [64]
    float* out = (float*)d_out;

    init_kernel<<<(N_SEQ * 32) / 256, 256>>>(emb, out);
    h0_kernel<<<dim3(N_SEQ / 32, DH / 32), 256>>>(Z, z2h_w, z2h_b);

    const size_t WL = (size_t)G3 * DH;            // per-layer w_hh / w_ih_rest slab
    const dim3 ggrid(N_SEQ / 128, DH / 32);

    for (int t = 1; t < TMAX; t++) {
        const int rb = (t - 1) & 1, wb = t & 1;
        gru_kernel<DE><<<ggrid, 256>>>(rb, wb, 0, w_ih0,      w_hh,          b_ih,          b_hh);
        gru_kernel<DH><<<ggrid, 256>>>(rb, wb, 1, w_ihr,      w_hh + WL,     b_ih + G3,     b_hh + G3);
        gru_kernel<DH><<<ggrid, 256>>>(rb, wb, 2, w_ihr + WL, w_hh + 2 * WL, b_ih + 2 * G3, b_hh + 2 * G3);
        head_kernel<<<N_SEQ / 8, 256>>>(wb, h2v_w, h2v_b, emb, out, t);
    }
    fin_kernel<<<N_SEQ / 256, 256>>>(out, out_size);
}